// round 16
// baseline (speedup 1.0000x reference)
#include <cuda_runtime.h>
#include <cuda_fp16.h>
#include <cstdint>

#define NBATCH 8
#define NN     2048
#define FF     128
#define UU     128
#define NP2    144      // padded B rows: 128 T cols + 1 Z col + 15 zero pad

__device__ __half g_Tt[NBATCH * NP2 * NN];

__device__ __forceinline__ uint32_t smem_u32(const void* p) {
    uint32_t a;
    asm("{ .reg .u64 t; cvta.to.shared.u64 t, %1; cvt.u32.u64 %0, t; }" : "=r"(a) : "l"(p));
    return a;
}
__device__ __forceinline__ void ldm_x4(uint32_t* r, uint32_t addr) {
    asm volatile("ldmatrix.sync.aligned.m8n8.x4.shared.b16 {%0,%1,%2,%3}, [%4];"
                 : "=r"(r[0]), "=r"(r[1]), "=r"(r[2]), "=r"(r[3]) : "r"(addr));
}
__device__ __forceinline__ void ldm_x4_t(uint32_t* r, uint32_t addr) {
    asm volatile("ldmatrix.sync.aligned.m8n8.x4.trans.shared.b16 {%0,%1,%2,%3}, [%4];"
                 : "=r"(r[0]), "=r"(r[1]), "=r"(r[2]), "=r"(r[3]) : "r"(addr));
}
__device__ __forceinline__ void mma16816(float* c, const uint32_t* a, const uint32_t* b) {
    asm volatile("mma.sync.aligned.m16n8k16.row.col.f32.f16.f16.f32 "
                 "{%0,%1,%2,%3}, {%4,%5,%6,%7}, {%8,%9}, {%0,%1,%2,%3};"
                 : "+f"(c[0]), "+f"(c[1]), "+f"(c[2]), "+f"(c[3])
                 : "r"(a[0]), "r"(a[1]), "r"(a[2]), "r"(a[3]), "r"(b[0]), "r"(b[1]));
}
__device__ __forceinline__ void sts128(uint32_t a, uint4 v) {
    asm volatile("st.shared.v4.b32 [%0], {%1,%2,%3,%4};"
                 :: "r"(a), "r"(v.x), "r"(v.y), "r"(v.z), "r"(v.w));
}
// chunk layout: [rows][64 halves] = rows * 128B, XOR swizzle on 16B units
__device__ __forceinline__ uint32_t cswz(int r, int kq) {
    return (uint32_t)(r * 128) + (uint32_t)(((kq ^ (r & 7)) & 7) << 4);
}
__device__ __forceinline__ uint32_t pk01(uint32_t x, uint32_t y) {
    return (x ? 0x3C00u : 0u) | (y ? 0x3C000000u : 0u);
}

// ---------------- kernel A (fused pre) smem offsets ----------------
#define A_XH   0u
#define A_XL   32768u
#define A_WH   65536u
#define A_WL   98304u
#define A_EPS  131072u
#define A_ES   197120u
#define A_AP   197632u
#define A_BF   199680u
#define A_W1   200192u
#define A_DSMEM 200704

// ---------------- kernel C smem offsets ----------------
#define C_A0 0u            // adj fp16 tile 128 x 64 halves = 16384
#define C_B0 16384u        // Tt tile 144 x 64 halves = 18432
#define C_A1 34816u
#define C_B1 51200u
#define C_DSMEM 69632      // epilogue eps 128 x 136 fp32 = 69632 (exact reuse)

// =====================================================================
// Kernel A (fused): T = X@Wf + bf (hi/lo fp16 HMMA), a = T.w1, e = exp(a),
// writes Tt[b][u][j] = e_j*T[j][u] fp16 K-major. (measured ~12-13 us)
// =====================================================================
__global__ void __launch_bounds__(512, 1) gat_pre_kernel(
    const float* __restrict__ X, const float* __restrict__ Wf,
    const float* __restrict__ bfv, const float* __restrict__ Ws)
{
    extern __shared__ char dsm[];
    uint32_t sb = smem_u32(dsm);
    int tid = threadIdx.x, lane = tid & 31, wid = tid >> 5;
    int wm = wid & 3, wn = wid >> 2;
    int b = blockIdx.x >> 4;
    int j0 = (blockIdx.x & 15) << 7;

    float* bfs = reinterpret_cast<float*>(dsm + A_BF);
    float* w1s = reinterpret_cast<float*>(dsm + A_W1);
    float* eps = reinterpret_cast<float*>(dsm + A_EPS);
    float* es  = reinterpret_cast<float*>(dsm + A_ES);
    float* apart = reinterpret_cast<float*>(dsm + A_AP);
    if (tid < 128) { bfs[tid] = bfv[tid]; w1s[tid] = Ws[tid]; }

    const float* xb = X + ((size_t)b * NN + j0) * FF;
    #pragma unroll
    for (int i = 0; i < 4; ++i) {
        int cid = tid + i * 512;
        int r = cid >> 4, kq16 = cid & 15;
        const float* src = xb + (size_t)r * FF + kq16 * 8;
        float4 v0 = *reinterpret_cast<const float4*>(src);
        float4 v1 = *reinterpret_cast<const float4*>(src + 4);
        float f[8] = {v0.x, v0.y, v0.z, v0.w, v1.x, v1.y, v1.z, v1.w};
        __half h[8], l[8];
        #pragma unroll
        for (int t = 0; t < 8; ++t) {
            h[t] = __float2half_rn(f[t]);
            l[t] = __float2half_rn(f[t] - __half2float(h[t]));
        }
        uint32_t off = (uint32_t)((kq16 >> 3) * 16384) + cswz(r, kq16 & 7);
        sts128(sb + A_XH + off, *reinterpret_cast<uint4*>(h));
        sts128(sb + A_XL + off, *reinterpret_cast<uint4*>(l));
    }
    #pragma unroll
    for (int i = 0; i < 4; ++i) {
        int cid = tid + i * 512;
        int f = cid >> 4, uq16 = cid & 15;
        const float* src = Wf + (size_t)f * UU + uq16 * 8;
        float4 v0 = *reinterpret_cast<const float4*>(src);
        float4 v1 = *reinterpret_cast<const float4*>(src + 4);
        float fv[8] = {v0.x, v0.y, v0.z, v0.w, v1.x, v1.y, v1.z, v1.w};
        __half h[8], l[8];
        #pragma unroll
        for (int t = 0; t < 8; ++t) {
            h[t] = __float2half_rn(fv[t]);
            l[t] = __float2half_rn(fv[t] - __half2float(h[t]));
        }
        uint32_t off = (uint32_t)((uq16 >> 3) * 16384) + cswz(f, uq16 & 7);
        sts128(sb + A_WH + off, *reinterpret_cast<uint4*>(h));
        sts128(sb + A_WL + off, *reinterpret_cast<uint4*>(l));
    }
    __syncthreads();

    float acc[2][4][4];
    #pragma unroll
    for (int mi = 0; mi < 2; ++mi)
        #pragma unroll
        for (int ni = 0; ni < 4; ++ni)
            #pragma unroll
            for (int t = 0; t < 4; ++t) acc[mi][ni][t] = 0.f;

    #pragma unroll
    for (int ks = 0; ks < 8; ++ks) {
        int kqa = ks * 2 + (lane >> 4);
        uint32_t offc = (uint32_t)((kqa >> 3) * 16384);
        uint32_t ah[2][4], al[2][4];
        #pragma unroll
        for (int mi = 0; mi < 2; ++mi) {
            int r = wm * 32 + mi * 16 + (lane & 15);
            uint32_t off = offc + cswz(r, kqa & 7);
            ldm_x4(ah[mi], sb + A_XH + off);
            ldm_x4(al[mi], sb + A_XL + off);
        }
        int g = lane >> 3;
        int f = ks * 16 + (g & 1) * 8 + (lane & 7);
        int ucnk = wn >> 1;
        #pragma unroll
        for (int p = 0; p < 2; ++p) {
            int uq = (wn & 1) * 4 + 2 * p + (g >> 1);
            uint32_t off = (uint32_t)(ucnk * 16384) + cswz(f, uq);
            uint32_t bh[4], bl[4];
            ldm_x4_t(bh, sb + A_WH + off);
            ldm_x4_t(bl, sb + A_WL + off);
            #pragma unroll
            for (int mi = 0; mi < 2; ++mi) {
                mma16816(acc[mi][2 * p],     ah[mi], bh + 0);
                mma16816(acc[mi][2 * p],     ah[mi], bl + 0);
                mma16816(acc[mi][2 * p],     al[mi], bh + 0);
                mma16816(acc[mi][2 * p + 1], ah[mi], bh + 2);
                mma16816(acc[mi][2 * p + 1], ah[mi], bl + 2);
                mma16816(acc[mi][2 * p + 1], al[mi], bh + 2);
            }
        }
    }

    float pr[2][2] = {{0.f, 0.f}, {0.f, 0.f}};
    #pragma unroll
    for (int mi = 0; mi < 2; ++mi)
        #pragma unroll
        for (int ni = 0; ni < 4; ++ni) {
            int r0 = wm * 32 + mi * 16 + (lane >> 2);
            int c0 = wn * 32 + ni * 8 + (lane & 3) * 2;
            float b0 = bfs[c0], b1 = bfs[c0 + 1];
            float w0 = w1s[c0], w1v = w1s[c0 + 1];
            float v00 = acc[mi][ni][0] + b0, v01 = acc[mi][ni][1] + b1;
            float v10 = acc[mi][ni][2] + b0, v11 = acc[mi][ni][3] + b1;
            eps[r0 * 129 + c0] = v00;       eps[r0 * 129 + c0 + 1] = v01;
            eps[(r0 + 8) * 129 + c0] = v10; eps[(r0 + 8) * 129 + c0 + 1] = v11;
            pr[mi][0] += v00 * w0 + v01 * w1v;
            pr[mi][1] += v10 * w0 + v11 * w1v;
        }
    #pragma unroll
    for (int mi = 0; mi < 2; ++mi)
        #pragma unroll
        for (int h = 0; h < 2; ++h) {
            pr[mi][h] += __shfl_xor_sync(0xFFFFFFFFu, pr[mi][h], 1);
            pr[mi][h] += __shfl_xor_sync(0xFFFFFFFFu, pr[mi][h], 2);
        }
    if ((lane & 3) == 0) {
        #pragma unroll
        for (int mi = 0; mi < 2; ++mi)
            #pragma unroll
            for (int h = 0; h < 2; ++h) {
                int r = wm * 32 + mi * 16 + h * 8 + (lane >> 2);
                apart[r * 4 + wn] = pr[mi][h];
            }
    }
    __syncthreads();
    if (tid < 128) {
        float a = apart[tid * 4] + apart[tid * 4 + 1] + apart[tid * 4 + 2] + apart[tid * 4 + 3];
        es[tid] = expf(a);
    }
    __syncthreads();

    __half* ttb = g_Tt + (size_t)b * NP2 * NN + j0;
    #pragma unroll
    for (int i = 0; i < 8; ++i) {
        int q = tid + i * 512;
        int u = q >> 5, jq = q & 31;
        __half t4[4];
        #pragma unroll
        for (int t = 0; t < 4; ++t) {
            int j = jq * 4 + t;
            t4[t] = __float2half_rn(eps[j * 129 + u] * es[j]);
        }
        *reinterpret_cast<uint2*>(ttb + (size_t)u * NN + jq * 4) = *reinterpret_cast<uint2*>(t4);
    }
    if (tid < 128) {
        ttb[(size_t)128 * NN + tid] = __float2half_rn(es[tid]);
        #pragma unroll
        for (int rr = 129; rr < NP2; ++rr)
            ttb[(size_t)rr * NN + tid] = __ushort_as_half((unsigned short)0);
    }
}

// =====================================================================
// Kernel C: R14 structure, retiled to 384 threads (12 warps, 4m x 3n,
// warp tile 32 x 48). Reg-prefetch A+B, double buffer, 2 syncs/chunk.
// Same ldsm/mma totals as R14, 1.5x warps per SMSP for latency cover.
// =====================================================================
__global__ void __launch_bounds__(384, 1) gat_main_kernel(
    const int* __restrict__ adj, float* __restrict__ out)
{
    extern __shared__ char dsm[];
    uint32_t sb = smem_u32(dsm);
    int tid = threadIdx.x, lane = tid & 31, wid = tid >> 5;
    int wm = wid & 3, wn = wid >> 2;       // rows 32*wm, cols 48*wn (wn 0..2)
    int b = blockIdx.x >> 4;
    int i0 = (blockIdx.x & 15) << 7;

    const int* adjb = adj + ((size_t)b * NN + i0) * NN;
    const __half* ttb = g_Tt + (size_t)b * NP2 * NN;

    float acc[2][6][4];
    #pragma unroll
    for (int mi = 0; mi < 2; ++mi)
        #pragma unroll
        for (int ni = 0; ni < 6; ++ni)
            #pragma unroll
            for (int t = 0; t < 4; ++t) acc[mi][ni][t] = 0.f;

    uint4 pa[6];   // adjacency prefetch: 3 slots x 2 uint4 (slot2 predicated)
    uint4 pb[3];   // Tt prefetch: 3 slots exact (1152 = 3*384)
    int pr_r[3], pr_kq[3], pn_n[3], pn_kq[3];
    bool pr_v[3];
    #pragma unroll
    for (int i = 0; i < 3; ++i) {
        int cid = tid + i * 384; pr_r[i] = cid >> 3; pr_kq[i] = cid & 7;
        pr_v[i] = cid < 1024;
    }
    #pragma unroll
    for (int i = 0; i < 3; ++i) {
        int cid = tid + i * 384; pn_n[i] = cid >> 3; pn_kq[i] = cid & 7;
    }

    // ---- prologue: load + store chunk 0
    #pragma unroll
    for (int i = 0; i < 3; ++i)
        if (pr_v[i]) {
            const int* src = adjb + (size_t)pr_r[i] * NN + pr_kq[i] * 8;
            pa[2 * i]     = *reinterpret_cast<const uint4*>(src);
            pa[2 * i + 1] = *reinterpret_cast<const uint4*>(src + 4);
        }
    #pragma unroll
    for (int i = 0; i < 3; ++i)
        pb[i] = *reinterpret_cast<const uint4*>(ttb + (size_t)pn_n[i] * NN + pn_kq[i] * 8);
    {
        uint32_t abase = sb + C_A0, bbase = sb + C_B0;
        #pragma unroll
        for (int i = 0; i < 3; ++i)
            if (pr_v[i]) {
                uint4 u0 = pa[2 * i], u1 = pa[2 * i + 1];
                uint4 v;
                v.x = pk01(u0.x, u0.y); v.y = pk01(u0.z, u0.w);
                v.z = pk01(u1.x, u1.y); v.w = pk01(u1.z, u1.w);
                sts128(abase + cswz(pr_r[i], pr_kq[i]), v);
            }
        #pragma unroll
        for (int i = 0; i < 3; ++i)
            sts128(bbase + cswz(pn_n[i], pn_kq[i]), pb[i]);
    }
    __syncthreads();

    for (int ch = 0; ch < NN / 64; ++ch) {
        int buf = ch & 1;
        uint32_t abase = sb + (buf ? C_A1 : C_A0);
        uint32_t bbase = sb + (buf ? C_B1 : C_B0);

        if (ch + 1 < NN / 64) {           // prefetch next chunk into regs
            int k0 = (ch + 1) * 64;
            #pragma unroll
            for (int i = 0; i < 3; ++i)
                if (pr_v[i]) {
                    const int* src = adjb + (size_t)pr_r[i] * NN + k0 + pr_kq[i] * 8;
                    pa[2 * i]     = *reinterpret_cast<const uint4*>(src);
                    pa[2 * i + 1] = *reinterpret_cast<const uint4*>(src + 4);
                }
            #pragma unroll
            for (int i = 0; i < 3; ++i)
                pb[i] = *reinterpret_cast<const uint4*>(ttb + (size_t)pn_n[i] * NN + k0 + pn_kq[i] * 8);
        }

        #pragma unroll
        for (int ks = 0; ks < 4; ++ks) {
            uint32_t af[2][4];
            int kqa = ks * 2 + (lane >> 4);
            #pragma unroll
            for (int mi = 0; mi < 2; ++mi) {
                int r = wm * 32 + mi * 16 + (lane & 15);
                ldm_x4(af[mi], abase + cswz(r, kqa));
            }
            uint32_t bf[6][2];
            int kqb = ks * 2 + ((lane >> 3) & 1);
            #pragma unroll
            for (int nb = 0; nb < 3; ++nb) {
                int n = wn * 48 + nb * 16 + ((lane >> 4) & 1) * 8 + (lane & 7);
                ldm_x4(&bf[nb * 2][0], bbase + cswz(n, kqb));
            }
            #pragma unroll
            for (int mi = 0; mi < 2; ++mi)
                #pragma unroll
                for (int ni = 0; ni < 6; ++ni)
                    mma16816(acc[mi][ni], af[mi], bf[ni]);
        }
        __syncthreads();

        if (ch + 1 < NN / 64) {
            uint32_t na  = sb + (buf ? C_A0 : C_A1);
            uint32_t nb2 = sb + (buf ? C_B0 : C_B1);
            #pragma unroll
            for (int i = 0; i < 3; ++i)
                if (pr_v[i]) {
                    uint4 u0 = pa[2 * i], u1 = pa[2 * i + 1];
                    uint4 v;
                    v.x = pk01(u0.x, u0.y); v.y = pk01(u0.z, u0.w);
                    v.z = pk01(u1.x, u1.y); v.w = pk01(u1.z, u1.w);
                    sts128(na + cswz(pr_r[i], pr_kq[i]), v);
                }
            #pragma unroll
            for (int i = 0; i < 3; ++i)
                sts128(nb2 + cswz(pn_n[i], pn_kq[i]), pb[i]);
            __syncthreads();
        }
    }

    // ---- epilogue: stage to smem (reuse buffers), divide by Z, store
    // wn==2,ni==5 covers pad cols 136-143 -> skip (never read).
    float* eps = reinterpret_cast<float*>(dsm);   // 128 x 136 fp32
    #pragma unroll
    for (int mi = 0; mi < 2; ++mi)
        #pragma unroll
        for (int ni = 0; ni < 6; ++ni) {
            if (wn == 2 && ni == 5) continue;
            int r0 = wm * 32 + mi * 16 + (lane >> 2);
            int c0 = wn * 48 + ni * 8 + (lane & 3) * 2;
            eps[r0 * 136 + c0]           = acc[mi][ni][0];
            eps[r0 * 136 + c0 + 1]       = acc[mi][ni][1];
            eps[(r0 + 8) * 136 + c0]     = acc[mi][ni][2];
            eps[(r0 + 8) * 136 + c0 + 1] = acc[mi][ni][3];
        }
    __syncthreads();
    float* ob = out + ((size_t)b * NN + i0) * UU;
    #pragma unroll
    for (int i = 0; i < 11; ++i) {
        int q = tid + i * 384;                 // 4096 float4 = 128 x 128 floats
        if (q < 4096) {
            int r = q >> 5, c = (q & 31) * 4;
            float inv = 1.0f / eps[r * 136 + 128];
            float4 v = *reinterpret_cast<const float4*>(eps + r * 136 + c);
            v.x *= inv; v.y *= inv; v.z *= inv; v.w *= inv;
            *reinterpret_cast<float4*>(ob + (size_t)r * UU + c) = v;
        }
    }
}

// =====================================================================
extern "C" void kernel_launch(void* const* d_in, const int* in_sizes, int n_in,
                              void* d_out, int out_size)
{
    const float* X   = (const float*)d_in[0];
    const int*   adj = (const int*)d_in[1];
    const float* Wf  = (const float*)d_in[2];
    const float* bfv = (const float*)d_in[3];
    const float* Ws  = (const float*)d_in[4];
    float* out = (float*)d_out;

    cudaFuncSetAttribute(gat_pre_kernel, cudaFuncAttributeMaxDynamicSharedMemorySize, A_DSMEM);
    cudaFuncSetAttribute(gat_main_kernel, cudaFuncAttributeMaxDynamicSharedMemorySize, C_DSMEM);

    gat_pre_kernel<<<128, 512, A_DSMEM>>>(X, Wf, bfv, Ws);
    gat_main_kernel<<<128, 384, C_DSMEM>>>(adj, out);
}

// round 17
// speedup vs baseline: 1.0709x; 1.0709x over previous
#include <cuda_runtime.h>
#include <cuda_fp16.h>
#include <cstdint>

#define NBATCH 8
#define NN     2048
#define FF     128
#define UU     128
#define NP2    144      // padded B rows: 128 T cols + 1 Z col + 15 zero pad

__device__ __half g_Tt[NBATCH * NP2 * NN];

__device__ __forceinline__ uint32_t smem_u32(const void* p) {
    uint32_t a;
    asm("{ .reg .u64 t; cvta.to.shared.u64 t, %1; cvt.u32.u64 %0, t; }" : "=r"(a) : "l"(p));
    return a;
}
__device__ __forceinline__ void ldm_x4(uint32_t* r, uint32_t addr) {
    asm volatile("ldmatrix.sync.aligned.m8n8.x4.shared.b16 {%0,%1,%2,%3}, [%4];"
                 : "=r"(r[0]), "=r"(r[1]), "=r"(r[2]), "=r"(r[3]) : "r"(addr));
}
__device__ __forceinline__ void ldm_x4_t(uint32_t* r, uint32_t addr) {
    asm volatile("ldmatrix.sync.aligned.m8n8.x4.trans.shared.b16 {%0,%1,%2,%3}, [%4];"
                 : "=r"(r[0]), "=r"(r[1]), "=r"(r[2]), "=r"(r[3]) : "r"(addr));
}
__device__ __forceinline__ void ldm_x2(uint32_t* r, uint32_t addr) {
    asm volatile("ldmatrix.sync.aligned.m8n8.x2.shared.b16 {%0,%1}, [%2];"
                 : "=r"(r[0]), "=r"(r[1]) : "r"(addr));
}
__device__ __forceinline__ void mma16816(float* c, const uint32_t* a, const uint32_t* b) {
    asm volatile("mma.sync.aligned.m16n8k16.row.col.f32.f16.f16.f32 "
                 "{%0,%1,%2,%3}, {%4,%5,%6,%7}, {%8,%9}, {%0,%1,%2,%3};"
                 : "+f"(c[0]), "+f"(c[1]), "+f"(c[2]), "+f"(c[3])
                 : "r"(a[0]), "r"(a[1]), "r"(a[2]), "r"(a[3]), "r"(b[0]), "r"(b[1]));
}
__device__ __forceinline__ void sts128(uint32_t a, uint4 v) {
    asm volatile("st.shared.v4.b32 [%0], {%1,%2,%3,%4};"
                 :: "r"(a), "r"(v.x), "r"(v.y), "r"(v.z), "r"(v.w));
}
// chunk layout: [rows][64 halves] = rows * 128B, XOR swizzle on 16B units
__device__ __forceinline__ uint32_t cswz(int r, int kq) {
    return (uint32_t)(r * 128) + (uint32_t)(((kq ^ (r & 7)) & 7) << 4);
}
__device__ __forceinline__ uint32_t pk01(uint32_t x, uint32_t y) {
    return (x ? 0x3C00u : 0u) | (y ? 0x3C000000u : 0u);
}

// ---------------- kernel A (fused pre, single fp16) smem offsets ----------------
#define A_XH   0u          // X fp16: 2 k-chunks x 16KB
#define A_WH   32768u      // Wf fp16 [f][u]: 2 u-chunks x 16KB
#define A_EPS  65536u      // T staging 128 x 129 fp32 = 66048
#define A_ES   131584u
#define A_AP   132096u
#define A_BF   134144u
#define A_W1   134656u
#define A_DSMEM 135168

// ---------------- kernel C smem offsets (K=128 chunks, 2 sub-chunks) ----------
#define C_A0 0u            // adj fp16: 2 subs x 16384 = 32768
#define C_A1 32768u
#define C_B0 65536u        // Tt: 2 subs x 18432 = 36864
#define C_B1 102400u
#define C_DSMEM 139264     // epilogue eps 128 x 136 fp32 = 69632 (reuse from 0)
#define ASUB 16384u
#define BSUB 18432u

// =====================================================================
// Kernel A (fused): T = X@Wf + bf (single fp16 HMMA), a = T.w1, e = exp(a),
// writes Tt[b][u][j] = e_j*T[j][u] fp16 K-major.
// =====================================================================
__global__ void __launch_bounds__(512, 1) gat_pre_kernel(
    const float* __restrict__ X, const float* __restrict__ Wf,
    const float* __restrict__ bfv, const float* __restrict__ Ws)
{
    extern __shared__ char dsm[];
    uint32_t sb = smem_u32(dsm);
    int tid = threadIdx.x, lane = tid & 31, wid = tid >> 5;
    int wm = wid & 3, wn = wid >> 2;
    int b = blockIdx.x >> 4;
    int j0 = (blockIdx.x & 15) << 7;

    float* bfs = reinterpret_cast<float*>(dsm + A_BF);
    float* w1s = reinterpret_cast<float*>(dsm + A_W1);
    float* eps = reinterpret_cast<float*>(dsm + A_EPS);
    float* es  = reinterpret_cast<float*>(dsm + A_ES);
    float* apart = reinterpret_cast<float*>(dsm + A_AP);
    if (tid < 128) { bfs[tid] = bfv[tid]; w1s[tid] = Ws[tid]; }

    const float* xb = X + ((size_t)b * NN + j0) * FF;
    #pragma unroll
    for (int i = 0; i < 4; ++i) {
        int cid = tid + i * 512;
        int r = cid >> 4, kq16 = cid & 15;
        const float* src = xb + (size_t)r * FF + kq16 * 8;
        float4 v0 = *reinterpret_cast<const float4*>(src);
        float4 v1 = *reinterpret_cast<const float4*>(src + 4);
        float f[8] = {v0.x, v0.y, v0.z, v0.w, v1.x, v1.y, v1.z, v1.w};
        __half h[8];
        #pragma unroll
        for (int t = 0; t < 8; ++t) h[t] = __float2half_rn(f[t]);
        uint32_t off = (uint32_t)((kq16 >> 3) * 16384) + cswz(r, kq16 & 7);
        sts128(sb + A_XH + off, *reinterpret_cast<uint4*>(h));
    }
    #pragma unroll
    for (int i = 0; i < 4; ++i) {
        int cid = tid + i * 512;
        int f = cid >> 4, uq16 = cid & 15;
        const float* src = Wf + (size_t)f * UU + uq16 * 8;
        float4 v0 = *reinterpret_cast<const float4*>(src);
        float4 v1 = *reinterpret_cast<const float4*>(src + 4);
        float fv[8] = {v0.x, v0.y, v0.z, v0.w, v1.x, v1.y, v1.z, v1.w};
        __half h[8];
        #pragma unroll
        for (int t = 0; t < 8; ++t) h[t] = __float2half_rn(fv[t]);
        uint32_t off = (uint32_t)((uq16 >> 3) * 16384) + cswz(f, uq16 & 7);
        sts128(sb + A_WH + off, *reinterpret_cast<uint4*>(h));
    }
    __syncthreads();

    float acc[2][4][4];
    #pragma unroll
    for (int mi = 0; mi < 2; ++mi)
        #pragma unroll
        for (int ni = 0; ni < 4; ++ni)
            #pragma unroll
            for (int t = 0; t < 4; ++t) acc[mi][ni][t] = 0.f;

    #pragma unroll
    for (int ks = 0; ks < 8; ++ks) {
        int kqa = ks * 2 + (lane >> 4);
        uint32_t offc = (uint32_t)((kqa >> 3) * 16384);
        uint32_t ah[2][4];
        #pragma unroll
        for (int mi = 0; mi < 2; ++mi) {
            int r = wm * 32 + mi * 16 + (lane & 15);
            ldm_x4(ah[mi], sb + A_XH + offc + cswz(r, kqa & 7));
        }
        int g = lane >> 3;
        int f = ks * 16 + (g & 1) * 8 + (lane & 7);
        int ucnk = wn >> 1;
        #pragma unroll
        for (int p = 0; p < 2; ++p) {
            int uq = (wn & 1) * 4 + 2 * p + (g >> 1);
            uint32_t off = (uint32_t)(ucnk * 16384) + cswz(f, uq);
            uint32_t bh[4];
            ldm_x4_t(bh, sb + A_WH + off);
            #pragma unroll
            for (int mi = 0; mi < 2; ++mi) {
                mma16816(acc[mi][2 * p],     ah[mi], bh + 0);
                mma16816(acc[mi][2 * p + 1], ah[mi], bh + 2);
            }
        }
    }

    float pr[2][2] = {{0.f, 0.f}, {0.f, 0.f}};
    #pragma unroll
    for (int mi = 0; mi < 2; ++mi)
        #pragma unroll
        for (int ni = 0; ni < 4; ++ni) {
            int r0 = wm * 32 + mi * 16 + (lane >> 2);
            int c0 = wn * 32 + ni * 8 + (lane & 3) * 2;
            float b0 = bfs[c0], b1 = bfs[c0 + 1];
            float w0 = w1s[c0], w1v = w1s[c0 + 1];
            float v00 = acc[mi][ni][0] + b0, v01 = acc[mi][ni][1] + b1;
            float v10 = acc[mi][ni][2] + b0, v11 = acc[mi][ni][3] + b1;
            eps[r0 * 129 + c0] = v00;       eps[r0 * 129 + c0 + 1] = v01;
            eps[(r0 + 8) * 129 + c0] = v10; eps[(r0 + 8) * 129 + c0 + 1] = v11;
            pr[mi][0] += v00 * w0 + v01 * w1v;
            pr[mi][1] += v10 * w0 + v11 * w1v;
        }
    #pragma unroll
    for (int mi = 0; mi < 2; ++mi)
        #pragma unroll
        for (int h = 0; h < 2; ++h) {
            pr[mi][h] += __shfl_xor_sync(0xFFFFFFFFu, pr[mi][h], 1);
            pr[mi][h] += __shfl_xor_sync(0xFFFFFFFFu, pr[mi][h], 2);
        }
    if ((lane & 3) == 0) {
        #pragma unroll
        for (int mi = 0; mi < 2; ++mi)
            #pragma unroll
            for (int h = 0; h < 2; ++h) {
                int r = wm * 32 + mi * 16 + h * 8 + (lane >> 2);
                apart[r * 4 + wn] = pr[mi][h];
            }
    }
    __syncthreads();
    if (tid < 128) {
        float a = apart[tid * 4] + apart[tid * 4 + 1] + apart[tid * 4 + 2] + apart[tid * 4 + 3];
        es[tid] = expf(a);
    }
    __syncthreads();

    __half* ttb = g_Tt + (size_t)b * NP2 * NN + j0;
    #pragma unroll
    for (int i = 0; i < 8; ++i) {
        int q = tid + i * 512;
        int u = q >> 5, jq = q & 31;
        __half t4[4];
        #pragma unroll
        for (int t = 0; t < 4; ++t) {
            int j = jq * 4 + t;
            t4[t] = __float2half_rn(eps[j * 129 + u] * es[j]);
        }
        *reinterpret_cast<uint2*>(ttb + (size_t)u * NN + jq * 4) = *reinterpret_cast<uint2*>(t4);
    }
    if (tid < 128) {
        ttb[(size_t)128 * NN + tid] = __float2half_rn(es[tid]);
        #pragma unroll
        for (int rr = 129; rr < NP2; ++rr)
            ttb[(size_t)rr * NN + tid] = __ushort_as_half((unsigned short)0);
    }
}

// =====================================================================
// Kernel C: R14 machinery, K-chunks widened to 128 (2 x 64 sub-chunks),
// ONE sync per 128-chunk (16 barriers total vs 64).
// grid 128, block 256, warps 4m x 2n (tile 32 x 72), reg-prefetch A+B.
// =====================================================================
__global__ void __launch_bounds__(256, 1) gat_main_kernel(
    const int* __restrict__ adj, float* __restrict__ out)
{
    extern __shared__ char dsm[];
    uint32_t sb = smem_u32(dsm);
    int tid = threadIdx.x, lane = tid & 31, wid = tid >> 5;
    int wm = wid & 3, wn = wid >> 2;       // rows 32*wm, cols 72*wn
    int b = blockIdx.x >> 4;
    int i0 = (blockIdx.x & 15) << 7;

    const int* adjb = adj + ((size_t)b * NN + i0) * NN;
    const __half* ttb = g_Tt + (size_t)b * NP2 * NN;

    float acc[2][9][4];
    #pragma unroll
    for (int mi = 0; mi < 2; ++mi)
        #pragma unroll
        for (int ni = 0; ni < 9; ++ni)
            #pragma unroll
            for (int t = 0; t < 4; ++t) acc[mi][ni][t] = 0.f;

    uint4 pa[8];   // adjacency prefetch: 4 slots x 2 uint4 (one 64-sub-chunk)
    uint4 pb[5];   // Tt prefetch (one 64-sub-chunk)
    int pr_r[4], pr_kq[4], pn_n[5], pn_kq[5];
    bool pn_v[5];
    #pragma unroll
    for (int i = 0; i < 4; ++i) {
        int cid = tid + i * 256; pr_r[i] = cid >> 3; pr_kq[i] = cid & 7;
    }
    #pragma unroll
    for (int i = 0; i < 5; ++i) {
        int cid = tid + i * 256; pn_n[i] = cid >> 3; pn_kq[i] = cid & 7;
        pn_v[i] = cid < NP2 * 8;
    }

    #define LDSUB(k0) do { \
        _Pragma("unroll") \
        for (int _i = 0; _i < 4; ++_i) { \
            const int* _src = adjb + (size_t)pr_r[_i] * NN + (k0) + pr_kq[_i] * 8; \
            pa[2*_i]     = *reinterpret_cast<const uint4*>(_src); \
            pa[2*_i + 1] = *reinterpret_cast<const uint4*>(_src + 4); \
        } \
        _Pragma("unroll") \
        for (int _i = 0; _i < 5; ++_i) \
            if (pn_v[_i]) \
                pb[_i] = *reinterpret_cast<const uint4*>(ttb + (size_t)pn_n[_i] * NN + (k0) + pn_kq[_i] * 8); \
    } while (0)

    #define STSUB(abase, bbase) do { \
        _Pragma("unroll") \
        for (int _i = 0; _i < 4; ++_i) { \
            uint4 _u0 = pa[2*_i], _u1 = pa[2*_i + 1]; \
            uint4 _v; \
            _v.x = pk01(_u0.x, _u0.y); _v.y = pk01(_u0.z, _u0.w); \
            _v.z = pk01(_u1.x, _u1.y); _v.w = pk01(_u1.z, _u1.w); \
            sts128((abase) + cswz(pr_r[_i], pr_kq[_i]), _v); \
        } \
        _Pragma("unroll") \
        for (int _i = 0; _i < 5; ++_i) \
            if (pn_v[_i]) sts128((bbase) + cswz(pn_n[_i], pn_kq[_i]), pb[_i]); \
    } while (0)

    #define DO_KS(ksIdx, abase, bbase) do { \
        uint32_t _af[2][4]; \
        int _kqa = (ksIdx) * 2 + (lane >> 4); \
        _Pragma("unroll") \
        for (int _mi = 0; _mi < 2; ++_mi) { \
            int _r = wm * 32 + _mi * 16 + (lane & 15); \
            ldm_x4(_af[_mi], (abase) + cswz(_r, _kqa)); \
        } \
        uint32_t _bf[9][2]; \
        int _kqb = (ksIdx) * 2 + ((lane >> 3) & 1); \
        _Pragma("unroll") \
        for (int _nb = 0; _nb < 4; ++_nb) { \
            int _n = wn * 72 + _nb * 16 + ((lane >> 4) & 1) * 8 + (lane & 7); \
            ldm_x4(&_bf[_nb * 2][0], (bbase) + cswz(_n, _kqb)); \
        } \
        { int _n = wn * 72 + 64 + (lane & 7); \
          ldm_x2(&_bf[8][0], (bbase) + cswz(_n, _kqb)); } \
        _Pragma("unroll") \
        for (int _mi = 0; _mi < 2; ++_mi) \
            _Pragma("unroll") \
            for (int _ni = 0; _ni < 9; ++_ni) \
                mma16816(acc[_mi][_ni], _af[_mi], _bf[_ni]); \
    } while (0)

    // ---- prologue: chunk 0 (both subs) -> buffer 0
    LDSUB(0);  STSUB(sb + C_A0, sb + C_B0);
    LDSUB(64); STSUB(sb + C_A0 + ASUB, sb + C_B0 + BSUB);
    __syncthreads();

    for (int ch = 0; ch < 16; ++ch) {
        int k0 = ch * 128;
        uint32_t Acur = sb + ((ch & 1) ? C_A1 : C_A0);
        uint32_t Bcur = sb + ((ch & 1) ? C_B1 : C_B0);
        uint32_t Anxt = sb + ((ch & 1) ? C_A0 : C_A1);
        uint32_t Bnxt = sb + ((ch & 1) ? C_B0 : C_B1);
        bool more = (ch < 15);

        if (more) LDSUB(k0 + 128);

        DO_KS(0, Acur, Bcur);
        DO_KS(1, Acur, Bcur);
        DO_KS(2, Acur, Bcur);
        DO_KS(3, Acur, Bcur);

        if (more) { STSUB(Anxt, Bnxt); LDSUB(k0 + 192); }

        DO_KS(0, Acur + ASUB, Bcur + BSUB);
        DO_KS(1, Acur + ASUB, Bcur + BSUB);
        DO_KS(2, Acur + ASUB, Bcur + BSUB);
        DO_KS(3, Acur + ASUB, Bcur + BSUB);

        if (more) STSUB(Anxt + ASUB, Bnxt + BSUB);
        __syncthreads();
    }

    // ---- epilogue: stage to smem (reuse buffers), divide by Z, store
    // wn==1,ni==8 covers pad cols 136-143 -> skip (never read).
    float* eps = reinterpret_cast<float*>(dsm);   // 128 x 136 fp32
    #pragma unroll
    for (int mi = 0; mi < 2; ++mi)
        #pragma unroll
        for (int ni = 0; ni < 9; ++ni) {
            if (wn == 1 && ni == 8) continue;
            int r0 = wm * 32 + mi * 16 + (lane >> 2);
            int c0 = wn * 72 + ni * 8 + (lane & 3) * 2;
            eps[r0 * 136 + c0]           = acc[mi][ni][0];
            eps[r0 * 136 + c0 + 1]       = acc[mi][ni][1];
            eps[(r0 + 8) * 136 + c0]     = acc[mi][ni][2];
            eps[(r0 + 8) * 136 + c0 + 1] = acc[mi][ni][3];
        }
    __syncthreads();
    float* ob = out + ((size_t)b * NN + i0) * UU;
    #pragma unroll
    for (int i = 0; i < 16; ++i) {
        int q = tid + i * 256;
        int r = q >> 5, c = (q & 31) * 4;
        float inv = 1.0f / eps[r * 136 + 128];
        float4 v = *reinterpret_cast<const float4*>(eps + r * 136 + c);
        v.x *= inv; v.y *= inv; v.z *= inv; v.w *= inv;
        *reinterpret_cast<float4*>(ob + (size_t)r * UU + c) = v;
    }
}

// =====================================================================
extern "C" void kernel_launch(void* const* d_in, const int* in_sizes, int n_in,
                              void* d_out, int out_size)
{
    const float* X   = (const float*)d_in[0];
    const int*   adj = (const int*)d_in[1];
    const float* Wf  = (const float*)d_in[2];
    const float* bfv = (const float*)d_in[3];
    const float* Ws  = (const float*)d_in[4];
    float* out = (float*)d_out;

    cudaFuncSetAttribute(gat_pre_kernel, cudaFuncAttributeMaxDynamicSharedMemorySize, A_DSMEM);
    cudaFuncSetAttribute(gat_main_kernel, cudaFuncAttributeMaxDynamicSharedMemorySize, C_DSMEM);

    gat_pre_kernel<<<128, 512, A_DSMEM>>>(X, Wf, bfv, Ws);
    gat_main_kernel<<<128, 256, C_DSMEM>>>(adj, out);
}